// round 1
// baseline (speedup 1.0000x reference)
#include <cuda_runtime.h>

// XrayTransforms: standardize -> soft-hist equalize -> 2x bilinear (=2x2 avg) -> normalize
// x: (2,1,512,512) f32, out: (2,1,256,256) f32

#define NB 256
#define HW 512
#define NPIX (HW*HW)          // 262144 per batch
#define RADIUS 12
// A = 1/(2*tau^2) = 5000, Delta = 1/255
#define TWO_A_D  39.21568627450980f   // 2*A*Delta
#define A_D2     0.07689350249903883f // A*Delta^2
#define RATIO_C  0.85745500f          // exp(-2*A*Delta^2)
#define INV255   (1.0f/255.0f)

__device__ int   g_min_bits;
__device__ int   g_max_bits;
__device__ float g_hist[2][NB];
__device__ float g_cdfn[2][NB];
__device__ float g_scale[2];   // [0]=min, [1]=1/(max-min+1e-6)

__global__ void k_init() {
    int t = threadIdx.x;
    if (t == 0) { g_min_bits = 0x7f800000; g_max_bits = 0; }
    for (int i = t; i < 2 * NB; i += blockDim.x) ((float*)g_hist)[i] = 0.0f;
}

__global__ void k_minmax(const float* __restrict__ x) {
    const float4* x4 = (const float4*)x;
    int n4 = (2 * NPIX) / 4;
    float mn = 1e30f, mx = -1e30f;
    for (int i = blockIdx.x * blockDim.x + threadIdx.x; i < n4; i += gridDim.x * blockDim.x) {
        float4 v = x4[i];
        mn = fminf(mn, fminf(fminf(v.x, v.y), fminf(v.z, v.w)));
        mx = fmaxf(mx, fmaxf(fmaxf(v.x, v.y), fmaxf(v.z, v.w)));
    }
    #pragma unroll
    for (int o = 16; o; o >>= 1) {
        mn = fminf(mn, __shfl_xor_sync(0xFFFFFFFFu, mn, o));
        mx = fmaxf(mx, __shfl_xor_sync(0xFFFFFFFFu, mx, o));
    }
    if ((threadIdx.x & 31) == 0) {
        atomicMin(&g_min_bits, __float_as_int(mn));  // all values >= 0: int order == float order
        atomicMax(&g_max_bits, __float_as_int(mx));
    }
}

__global__ void k_scale() {
    float mn = __int_as_float(g_min_bits);
    float mx = __int_as_float(g_max_bits);
    g_scale[0] = mn;
    g_scale[1] = 1.0f / (mx - mn + 1e-6f);
}

__global__ void k_hist(const float* __restrict__ x) {
    __shared__ float sh[NB];
    const int b = blockIdx.y;
    for (int i = threadIdx.x; i < NB; i += blockDim.x) sh[i] = 0.0f;
    __syncthreads();

    const float mn  = g_scale[0];
    const float inv = g_scale[1];
    const float4* xb = (const float4*)(x + b * NPIX);
    const int n4 = NPIX / 4;
    const int stride = gridDim.x * blockDim.x;

    for (int idx = blockIdx.x * blockDim.x + threadIdx.x; idx < n4; idx += stride) {
        float4 p4 = xb[idx];
        float vv[4] = {p4.x, p4.y, p4.z, p4.w};
        #pragma unroll
        for (int q = 0; q < 4; q++) {
            float v = (vv[q] - mn) * inv;
            int k = __float2int_rn(v * 255.0f);
            int jlo = k - RADIUS;
            float d0 = v - (float)jlo * INV255;
            float w = __expf(-5000.0f * d0 * d0);
            float r = __expf(TWO_A_D * d0 - A_D2);
            #pragma unroll
            for (int s = 0; s < 2 * RADIUS + 1; s++) {
                int j = jlo + s;
                if (j >= 0 && j < NB) atomicAdd(&sh[j], w);
                w *= r;
                r *= RATIO_C;
            }
        }
    }
    __syncthreads();
    for (int i = threadIdx.x; i < NB; i += blockDim.x)
        atomicAdd(&g_hist[b][i], sh[i]);
}

__global__ void k_cdf() {
    __shared__ float s[NB];
    int b = blockIdx.x, t = threadIdx.x;
    s[t] = g_hist[b][t];
    __syncthreads();
    // Hillis-Steele inclusive scan
    #pragma unroll
    for (int o = 1; o < NB; o <<= 1) {
        float add = (t >= o) ? s[t - o] : 0.0f;
        __syncthreads();
        s[t] += add;
        __syncthreads();
    }
    float total = s[NB - 1];
    float invS  = 1.0f / (total + 1e-10f);
    float cdf   = s[t] * invS;
    float cdf0  = s[0] * invS;
    g_cdfn[b][t] = (cdf - cdf0) / (1.0f - cdf0 + 1e-10f);
}

__device__ __forceinline__ float equalize_px(float xraw, float mn, float inv,
                                             const float* __restrict__ cdfn) {
    float v = (xraw - mn) * inv;
    int k = __float2int_rn(v * 255.0f);
    int jlo = k - RADIUS;
    float d0 = v - (float)jlo * INV255;
    float w = __expf(-5000.0f * d0 * d0);
    float r = __expf(TWO_A_D * d0 - A_D2);
    float num = 0.0f, den = 0.0f;
    #pragma unroll
    for (int s = 0; s < 2 * RADIUS + 1; s++) {
        int j = jlo + s;
        if (j >= 0 && j < NB) {
            num += w * cdfn[j];
            den += w;
        }
        w *= r;
        r *= RATIO_C;
    }
    return num / (den + 1e-10f);
}

__global__ void k_out(const float* __restrict__ x, float* __restrict__ out) {
    __shared__ float cdfn[NB];
    int idx = blockIdx.x * blockDim.x + threadIdx.x;   // 131072 threads, 1 output px each
    int b = idx >> 16;                                  // block fully within one batch
    for (int i = threadIdx.x; i < NB; i += blockDim.x) cdfn[i] = g_cdfn[b][i];
    __syncthreads();

    int rem = idx & 0xFFFF;
    int oy = rem >> 8;
    int ox = rem & 255;
    const float* base = x + b * NPIX;
    float2 t0 = ((const float2*)(base + (2 * oy)     * HW))[ox];
    float2 t1 = ((const float2*)(base + (2 * oy + 1) * HW))[ox];

    float mn  = g_scale[0];
    float inv = g_scale[1];
    float e = equalize_px(t0.x, mn, inv, cdfn)
            + equalize_px(t0.y, mn, inv, cdfn)
            + equalize_px(t1.x, mn, inv, cdfn)
            + equalize_px(t1.y, mn, inv, cdfn);
    out[idx] = (0.25f * e - 0.15f) / 0.1f;
}

extern "C" void kernel_launch(void* const* d_in, const int* in_sizes, int n_in,
                              void* d_out, int out_size) {
    const float* x = (const float*)d_in[0];
    float* out = (float*)d_out;
    k_init<<<1, 256>>>();
    k_minmax<<<256, 256>>>(x);
    k_scale<<<1, 1>>>();
    k_hist<<<dim3(256, 2), 256>>>(x);
    k_cdf<<<2, NB>>>();
    k_out<<<512, 256>>>(x, out);
}